// round 3
// baseline (speedup 1.0000x reference)
#include <cuda_runtime.h>
#include <cuda_bf16.h>
#include <math.h>

// Problem constants
#define BB 32
#define HH 64
#define WW 64
#define DD 8     // input capsule dim
#define CC 8     // input capsule types
#define DIMO 8   // output capsule dim
#define NCHO 8   // output capsule types

typedef unsigned long long ull;

// Packed fp32x2 helpers (Blackwell sm_103a): one SASS FFMA2 per pair.
#define FFMA2(d, a, b, c) \
    asm("fma.rn.f32x2 %0, %1, %2, %3;" : "=l"(d) : "l"(a), "l"(b), "l"(c))
#define PACK2(dst, lo, hi) \
    asm("mov.b64 %0, {%1, %2};" : "=l"(dst) : "f"(lo), "f"(hi))
#define UNPACK2(lo, hi, src) \
    asm("mov.b64 {%0, %1}, %2;" : "=f"(lo), "=f"(hi) : "l"(src))

// v scratch: [B][H][W][n*8+d]  (group-major for FeaExt)
__device__ float g_v[BB * HH * WW * 64];

// ---------------------------------------------------------------------------
// Kernel 1: ConvTrans (grouped 3x3) + attention softmax + weighted sum -> v
// Block: 8x8 pixel tile. blockDim (64, 8) = 512 threads.
// ---------------------------------------------------------------------------
// Dynamic smem (floats):
//   s_in : 10*10*64 = 6400
//   s_u  : 64*512   = 32768   u[pix][(d*8+c)*8 + n]
//   s_w  : 8*512    = 4096    one 3x3-tap ConvTrans weight slab
//   s_lg : 64*64    = 4096    attention logits [pix][o*8+n]
//   s_at : 64*64    = 4096    AW staging, then attention weights [pix][o*8+n]
#define K1_SMEM_FLOATS (6400 + 32768 + 4096 + 4096 + 4096)
#define K1_SMEM_BYTES  (K1_SMEM_FLOATS * 4)

__global__ __launch_bounds__(512, 1)
void convcaps_k1(const float* __restrict__ x,    // [B,H,W,D,C]  ch = d*8+c
                 const float* __restrict__ AW,   // [D,C,64]     dc*64 + n*8+o
                 const float* __restrict__ CTW,  // [9,8,512]    tap*4096 + din*512 + (c*64+dh*8+n)
                 const float* __restrict__ CTB)  // [512]
{
    extern __shared__ float sm[];
    float* s_in = sm;                 // 6400
    float* s_u  = s_in + 6400;        // 32768
    float* s_w  = s_u + 32768;        // 4096
    float* s_lg = s_w + 4096;         // 4096
    float* s_at = s_lg + 4096;        // 4096

    const int tx = threadIdx.x;       // 0..63
    const int ty = threadIdx.y;       // 0..7
    const int tid = ty * 64 + tx;

    const int b  = blockIdx.z;
    const int h0 = blockIdx.y * 8;
    const int w0 = blockIdx.x * 8;

    // ---- load input tile with halo (zero pad): 10x10 x 64ch ----
    for (int i = tid; i < 10 * 10 * 16; i += 512) {
        int q   = i & 15;
        int col = (i >> 4) % 10;
        int row = i / 160;
        int gh = h0 + row - 1;
        int gw = w0 + col - 1;
        float4 val = make_float4(0.f, 0.f, 0.f, 0.f);
        if ((unsigned)gh < (unsigned)HH && (unsigned)gw < (unsigned)WW) {
            val = *(const float4*)(x + (((size_t)(b * HH + gh) * WW + gw) * 64) + q * 4);
        }
        *(float4*)(s_in + (row * 10 + col) * 64 + q * 4) = val;
    }

    // ---- ConvTrans accumulators, packed over n: acc2[py][j] = (n=2j, n=2j+1) ----
    const int c  = tx >> 3;
    const int dh = tx & 7;

    ull acc2[8][4];
    {
        const float4* bp = (const float4*)(CTB + c * 64 + dh * 8);
        float4 b0 = __ldg(bp), b1 = __ldg(bp + 1);
        ull bias2[4];
        PACK2(bias2[0], b0.x, b0.y);
        PACK2(bias2[1], b0.z, b0.w);
        PACK2(bias2[2], b1.x, b1.y);
        PACK2(bias2[3], b1.z, b1.w);
        #pragma unroll
        for (int p = 0; p < 8; p++)
            #pragma unroll
            for (int j = 0; j < 4; j++)
                acc2[p][j] = bias2[j];
    }

    for (int tap = 0; tap < 9; tap++) {
        __syncthreads();  // also covers s_in readiness on first iter
        // stage this tap's weights: 4096 floats
        {
            const float4* wp = (const float4*)(CTW) + tap * 1024;
            for (int i = tid; i < 1024; i += 512)
                ((float4*)s_w)[i] = __ldg(wp + i);
        }
        __syncthreads();

        const int ky = tap / 3, kx = tap % 3;
        #pragma unroll
        for (int din = 0; din < 8; din++) {
            const ulonglong2* wp = (const ulonglong2*)(s_w + din * 512 + c * 64 + dh * 8);
            ulonglong2 wA = wp[0], wB = wp[1];
            ull w2[4] = {wA.x, wA.y, wB.x, wB.y};
            const float* inb = s_in + (ky * 10 + ty + kx) * 64 + din * 8 + c;
            #pragma unroll
            for (int py = 0; py < 8; py++) {
                float iv = inb[py * 640];
                ull iv2; PACK2(iv2, iv, iv);
                #pragma unroll
                for (int j = 0; j < 4; j++)
                    FFMA2(acc2[py][j], iv2, w2[j], acc2[py][j]);
            }
        }
    }

    // ---- store u to smem: s_u[pix][(dh*8+c)*8 + n] ----
    #pragma unroll
    for (int py = 0; py < 8; py++) {
        float r[8];
        #pragma unroll
        for (int j = 0; j < 4; j++)
            UNPACK2(r[2 * j], r[2 * j + 1], acc2[py][j]);
        float* up = s_u + (py * 8 + ty) * 512 + (dh * 8 + c) * 8;
        *(float4*)(up)     = make_float4(r[0], r[1], r[2], r[3]);
        *(float4*)(up + 4) = make_float4(r[4], r[5], r[6], r[7]);
    }
    // stage AW into s_at (4096 floats = 1024 float4; 2 per thread)
    {
        const float4* ap = (const float4*)AW;
        ((float4*)s_at)[tid]       = __ldg(ap + tid);
        ((float4*)s_at)[tid + 512] = __ldg(ap + tid + 512);
    }
    __syncthreads();

    // ---- attention logits: thread = (o, n), 8 pixels (pix = k*8+ty) ----
    {
        const int o = tx >> 3, n = tx & 7;
        float lg[8] = {0.f, 0.f, 0.f, 0.f, 0.f, 0.f, 0.f, 0.f};
        #pragma unroll 4
        for (int dc = 0; dc < 64; dc++) {
            float a = s_at[dc * 64 + n * 8 + o];
            #pragma unroll
            for (int k = 0; k < 8; k++)
                lg[k] = fmaf(s_u[(k * 8 + ty) * 512 + dc * 8 + n], a, lg[k]);
        }
        #pragma unroll
        for (int k = 0; k < 8; k++)
            s_lg[(k * 8 + ty) * 64 + o * 8 + n] = lg[k];
    }
    __syncthreads();

    // ---- softmax over o: thread (o,n) writes att[o][n] into s_at ----
    {
        const int o = tx >> 3, n = tx & 7;
        #pragma unroll
        for (int k = 0; k < 8; k++) {
            const float* lp = s_lg + (k * 8 + ty) * 64 + n;
            float l[8];
            float m = -1e30f;
            #pragma unroll
            for (int j = 0; j < 8; j++) { l[j] = lp[j * 8]; m = fmaxf(m, l[j]); }
            float s = 0.f;
            float eo = 0.f;
            #pragma unroll
            for (int j = 0; j < 8; j++) {
                float e = __expf(l[j] - m);
                s += e;
                if (j == o) eo = e;
            }
            s_at[(k * 8 + ty) * 64 + o * 8 + n] = eo / s;
        }
    }
    __syncthreads();

    // ---- v[d][n] = sum_o u[d][o][n] * att[o][n]; write g_v ch = n*8+d ----
    {
        const int d = tx >> 3, n = tx & 7;
        #pragma unroll
        for (int k = 0; k < 8; k++) {
            const int pix = k * 8 + ty;
            float v = 0.f;
            #pragma unroll
            for (int o = 0; o < 8; o++)
                v = fmaf(s_u[pix * 512 + (d * 8 + o) * 8 + n],
                         s_at[pix * 64 + o * 8 + n], v);
            int gh = h0 + k, gw = w0 + ty;
            g_v[((size_t)(b * HH + gh) * WW + gw) * 64 + n * 8 + d] = v;
        }
    }
}

// ---------------------------------------------------------------------------
// Kernel 2: FeaExt (grouped 3x3) + ReLU + CapsAct (grouped 1x1) -> out
// Block: 8x8 tile, 512 threads: thread = (pixel 0..63, n 0..7)
// Vectorized smem reads + packed FFMA2.
// ---------------------------------------------------------------------------
__global__ __launch_bounds__(512, 2)
void convcaps_k2(const float* __restrict__ FW,  // [9,8,64]  tap*512 + d*64 + (n*8+e)
                 const float* __restrict__ FB,  // [64]
                 const float* __restrict__ CW,  // [8,64]    e*64 + (n*8+f)
                 const float* __restrict__ CB,  // [64]
                 float* __restrict__ out)       // [B,H,W,64] ch = f*8+n
{
    __shared__ float s_v[10 * 10 * 64];   // 6400
    __shared__ float s_fw[9 * 8 * 64];    // 4608
    __shared__ float s_cw[8 * 64];        // 512
    __shared__ float s_fb[64];
    __shared__ float s_cb[64];

    const int tid = threadIdx.x;
    const int b  = blockIdx.z;
    const int h0 = blockIdx.y * 8;
    const int w0 = blockIdx.x * 8;

    // load v tile with halo
    for (int i = tid; i < 10 * 10 * 16; i += 512) {
        int q   = i & 15;
        int col = (i >> 4) % 10;
        int row = i / 160;
        int gh = h0 + row - 1;
        int gw = w0 + col - 1;
        float4 val = make_float4(0.f, 0.f, 0.f, 0.f);
        if ((unsigned)gh < (unsigned)HH && (unsigned)gw < (unsigned)WW) {
            val = *(const float4*)(g_v + (((size_t)(b * HH + gh) * WW + gw) * 64) + q * 4);
        }
        *(float4*)(s_v + (row * 10 + col) * 64 + q * 4) = val;
    }
    // load weights
    for (int i = tid; i < 1152; i += 512) ((float4*)s_fw)[i] = __ldg((const float4*)FW + i);
    if (tid < 128) ((float4*)s_cw)[tid] = __ldg((const float4*)CW + tid);
    if (tid < 64) { s_fb[tid] = __ldg(FB + tid); s_cb[tid] = __ldg(CB + tid); }
    __syncthreads();

    const int pix = tid >> 3;      // 0..63
    const int n   = tid & 7;
    const int pr = pix >> 3, pc = pix & 7;

    // FeaExt accumulators packed over e
    ull h1_2[4];
    {
        const float4* fb = (const float4*)(s_fb + n * 8);
        float4 f0 = fb[0], f1 = fb[1];
        PACK2(h1_2[0], f0.x, f0.y);
        PACK2(h1_2[1], f0.z, f0.w);
        PACK2(h1_2[2], f1.x, f1.y);
        PACK2(h1_2[3], f1.z, f1.w);
    }

    #pragma unroll
    for (int tap = 0; tap < 9; tap++) {
        const int ky = tap / 3, kx = tap % 3;
        const float4* vp = (const float4*)(s_v + ((pr + ky) * 10 + pc + kx) * 64 + n * 8);
        float4 va = vp[0], vb = vp[1];
        float iv[8] = {va.x, va.y, va.z, va.w, vb.x, vb.y, vb.z, vb.w};
        #pragma unroll
        for (int d = 0; d < 8; d++) {
            ull iv2; PACK2(iv2, iv[d], iv[d]);
            const ulonglong2* wp = (const ulonglong2*)(s_fw + (tap * 8 + d) * 64 + n * 8);
            ulonglong2 wA = wp[0], wB = wp[1];
            FFMA2(h1_2[0], iv2, wA.x, h1_2[0]);
            FFMA2(h1_2[1], iv2, wA.y, h1_2[1]);
            FFMA2(h1_2[2], iv2, wB.x, h1_2[2]);
            FFMA2(h1_2[3], iv2, wB.y, h1_2[3]);
        }
    }
    float h1[8];
    #pragma unroll
    for (int j = 0; j < 4; j++)
        UNPACK2(h1[2 * j], h1[2 * j + 1], h1_2[j]);
    #pragma unroll
    for (int e = 0; e < 8; e++) h1[e] = fmaxf(h1[e], 0.f);

    // CapsAct, packed over f
    ull h2_2[4];
    {
        const float4* cb = (const float4*)(s_cb + n * 8);
        float4 c0 = cb[0], c1 = cb[1];
        PACK2(h2_2[0], c0.x, c0.y);
        PACK2(h2_2[1], c0.z, c0.w);
        PACK2(h2_2[2], c1.x, c1.y);
        PACK2(h2_2[3], c1.z, c1.w);
    }
    #pragma unroll
    for (int e = 0; e < 8; e++) {
        ull he2; PACK2(he2, h1[e], h1[e]);
        const ulonglong2* cw = (const ulonglong2*)(s_cw + e * 64 + n * 8);
        ulonglong2 cA = cw[0], cB = cw[1];
        FFMA2(h2_2[0], he2, cA.x, h2_2[0]);
        FFMA2(h2_2[1], he2, cA.y, h2_2[1]);
        FFMA2(h2_2[2], he2, cB.x, h2_2[2]);
        FFMA2(h2_2[3], he2, cB.y, h2_2[3]);
    }

    float h2[8];
    #pragma unroll
    for (int j = 0; j < 4; j++)
        UNPACK2(h2[2 * j], h2[2 * j + 1], h2_2[j]);

    const int gh = h0 + pr, gw = w0 + pc;
    float* ob = out + ((size_t)(b * HH + gh) * WW + gw) * 64;
    #pragma unroll
    for (int f = 0; f < 8; f++)
        ob[f * 8 + n] = h2[f];
}

// ---------------------------------------------------------------------------
extern "C" void kernel_launch(void* const* d_in, const int* in_sizes, int n_in,
                              void* d_out, int out_size) {
    (void)in_sizes; (void)n_in; (void)out_size;
    const float* x   = (const float*)d_in[0];
    const float* AW  = (const float*)d_in[1];
    const float* CTW = (const float*)d_in[2];
    const float* CTB = (const float*)d_in[3];
    const float* FW  = (const float*)d_in[4];
    const float* FB  = (const float*)d_in[5];
    const float* CW  = (const float*)d_in[6];
    const float* CB  = (const float*)d_in[7];

    cudaFuncSetAttribute(convcaps_k1,
                         cudaFuncAttributeMaxDynamicSharedMemorySize, K1_SMEM_BYTES);

    dim3 grid(WW / 8, HH / 8, BB);
    convcaps_k1<<<grid, dim3(64, 8), K1_SMEM_BYTES>>>(x, AW, CTW, CTB);
    convcaps_k2<<<grid, 512>>>(FW, FB, CW, CB, (float*)d_out);
}

// round 5
// speedup vs baseline: 1.0191x; 1.0191x over previous
#include <cuda_runtime.h>
#include <cuda_bf16.h>
#include <math.h>

// Problem constants
#define BB 32
#define HH 64
#define WW 64

typedef unsigned long long ull;

// Packed fp32x2 helpers (Blackwell sm_103a)
#define FFMA2(d, a, b, c) \
    asm("fma.rn.f32x2 %0, %1, %2, %3;" : "=l"(d) : "l"(a), "l"(b), "l"(c))
#define PACK2(dst, lo, hi) \
    asm("mov.b64 %0, {%1, %2};" : "=l"(dst) : "f"(lo), "f"(hi))
#define UNPACK2(lo, hi, src) \
    asm("mov.b64 {%0, %1}, %2;" : "=f"(lo), "=f"(hi) : "l"(src))

// v scratch: [B][H][W][n*8+d]
__device__ float g_v[BB * HH * WW * 64];

// ---------------------------------------------------------------------------
// Kernel 1: ConvTrans (grouped 3x3) + attention softmax + weighted sum -> v
// Block: 8x8 pixel tile. blockDim (64, 16) = 1024 threads.
//   tx = c*8+dh ; ty 0..15 -> thread owns pixels {ty, ty+16, ty+32, ty+48}
// Double-buffered per-tap weight slabs (prefetch to regs, STS into alt buf).
// ---------------------------------------------------------------------------
// smem (floats): s_in 6400 | s_u 32768 | s_w 2*4096 | s_lg 4096 | s_at 4096
#define K1_SMEM_FLOATS (6400 + 32768 + 8192 + 4096 + 4096)
#define K1_SMEM_BYTES  (K1_SMEM_FLOATS * 4)

__global__ __launch_bounds__(1024, 1)
void convcaps_k1(const float* __restrict__ x,    // [B,H,W,64] ch = d*8+c
                 const float* __restrict__ AW,   // [64 dc][64] dc*64 + n*8+o
                 const float* __restrict__ CTW,  // [9][8 din][512] 512=c*64+dh*8+n
                 const float* __restrict__ CTB)  // [512]
{
    extern __shared__ float sm[];
    float* s_in = sm;                 // 6400
    float* s_u  = s_in + 6400;        // 32768   u[pix][(dh*8+c)*8+n]
    float* s_w  = s_u + 32768;        // 8192    two 4096-float slabs
    float* s_lg = s_w + 8192;         // 4096
    float* s_at = s_lg + 4096;        // 4096

    const int tx = threadIdx.x;       // 0..63
    const int ty = threadIdx.y;       // 0..15
    const int tid = ty * 64 + tx;     // 0..1023

    const int b  = blockIdx.z;
    const int h0 = blockIdx.y * 8;
    const int w0 = blockIdx.x * 8;

    // ---- load input tile with halo: 10x10x64 ----
    for (int i = tid; i < 10 * 10 * 16; i += 1024) {
        int q   = i & 15;
        int col = (i >> 4) % 10;
        int row = i / 160;
        int gh = h0 + row - 1;
        int gw = w0 + col - 1;
        float4 val = make_float4(0.f, 0.f, 0.f, 0.f);
        if ((unsigned)gh < (unsigned)HH && (unsigned)gw < (unsigned)WW)
            val = *(const float4*)(x + (((size_t)(b * HH + gh) * WW + gw) * 64) + q * 4);
        *(float4*)(s_in + (row * 10 + col) * 64 + q * 4) = val;
    }

    const int c  = tx >> 3;
    const int dh = tx & 7;
    const int r0 = ty >> 3;           // base row (0/1)
    const int cw = ty & 7;            // column

    // accumulators: 4 pixels x 8 n (packed)
    ull acc2[4][4];
    {
        const float4* bp = (const float4*)(CTB + c * 64 + dh * 8);
        float4 b0 = __ldg(bp), b1 = __ldg(bp + 1);
        ull bias2[4];
        PACK2(bias2[0], b0.x, b0.y);
        PACK2(bias2[1], b0.z, b0.w);
        PACK2(bias2[2], b1.x, b1.y);
        PACK2(bias2[3], b1.z, b1.w);
        #pragma unroll
        for (int p = 0; p < 4; p++)
            #pragma unroll
            for (int j = 0; j < 4; j++)
                acc2[p][j] = bias2[j];
    }

    // stage tap-0 weight slab (4096 floats = 1024 float4, one per thread)
    {
        float4 w0 = __ldg((const float4*)CTW + tid);
        ((float4*)s_w)[tid] = w0;
    }
    __syncthreads();

    for (int tap = 0; tap < 9; tap++) {
        float4 wn;
        if (tap < 8)
            wn = __ldg((const float4*)CTW + (tap + 1) * 1024 + tid);

        const float* wslab = s_w + (tap & 1) * 4096;
        const int ky = tap / 3, kx = tap % 3;
        const float* inb0 = s_in + ((r0 + ky) * 10 + cw + kx) * 64 + c;

        #pragma unroll
        for (int din = 0; din < 8; din++) {
            const ulonglong2* wp = (const ulonglong2*)(wslab + din * 512 + c * 64 + dh * 8);
            ulonglong2 wA = wp[0], wB = wp[1];
            ull w2[4] = {wA.x, wA.y, wB.x, wB.y};
            const float* inb = inb0 + din * 8;
            #pragma unroll
            for (int py = 0; py < 4; py++) {
                float iv = inb[py * 1280];     // +2 rows per py
                ull iv2; PACK2(iv2, iv, iv);
                #pragma unroll
                for (int j = 0; j < 4; j++)
                    FFMA2(acc2[py][j], iv2, w2[j], acc2[py][j]);
            }
        }

        if (tap < 8)
            ((float4*)(s_w + ((tap + 1) & 1) * 4096))[tid] = wn;
        __syncthreads();
    }

    // ---- store u: s_u[pix][(dh*8+c)*8 + n], pix = py*16 + ty ----
    #pragma unroll
    for (int py = 0; py < 4; py++) {
        float r[8];
        #pragma unroll
        for (int j = 0; j < 4; j++)
            UNPACK2(r[2 * j], r[2 * j + 1], acc2[py][j]);
        float* up = s_u + (py * 16 + ty) * 512 + (dh * 8 + c) * 8;
        *(float4*)(up)     = make_float4(r[0], r[1], r[2], r[3]);
        *(float4*)(up + 4) = make_float4(r[4], r[5], r[6], r[7]);
    }
    // stage AW into s_at (4096 floats = 1024 float4, one per thread)
    ((float4*)s_at)[tid] = __ldg((const float4*)AW + tid);
    __syncthreads();

    // ---- attention logits: thread = (o,n) x 4 pixels ----
    {
        const int o = tx >> 3, n = tx & 7;
        float lg[4] = {0.f, 0.f, 0.f, 0.f};
        #pragma unroll 4
        for (int dc = 0; dc < 64; dc++) {
            float a = s_at[dc * 64 + n * 8 + o];
            #pragma unroll
            for (int k = 0; k < 4; k++)
                lg[k] = fmaf(s_u[(k * 16 + ty) * 512 + dc * 8 + n], a, lg[k]);
        }
        #pragma unroll
        for (int k = 0; k < 4; k++)
            s_lg[(k * 16 + ty) * 64 + o * 8 + n] = lg[k];
    }
    __syncthreads();

    // ---- softmax over o: thread (o,n) writes att into s_at ----
    {
        const int o = tx >> 3, n = tx & 7;
        #pragma unroll
        for (int k = 0; k < 4; k++) {
            const float* lp = s_lg + (k * 16 + ty) * 64 + n;
            float l[8];
            float m = -1e30f;
            #pragma unroll
            for (int j = 0; j < 8; j++) { l[j] = lp[j * 8]; m = fmaxf(m, l[j]); }
            float s = 0.f, eo = 0.f;
            #pragma unroll
            for (int j = 0; j < 8; j++) {
                float e = __expf(l[j] - m);
                s += e;
                if (j == o) eo = e;
            }
            s_at[(k * 16 + ty) * 64 + o * 8 + n] = eo / s;
        }
    }
    __syncthreads();

    // ---- v[d][n] = sum_o u * att ; write g_v ch = n*8+d ----
    {
        const int d = tx >> 3, n = tx & 7;
        #pragma unroll
        for (int k = 0; k < 4; k++) {
            const int pix = k * 16 + ty;
            float v = 0.f;
            #pragma unroll
            for (int o = 0; o < 8; o++)
                v = fmaf(s_u[pix * 512 + (d * 8 + o) * 8 + n],
                         s_at[pix * 64 + o * 8 + n], v);
            int gh = h0 + (pix >> 3), gw = w0 + (pix & 7);
            g_v[((size_t)(b * HH + gh) * WW + gw) * 64 + n * 8 + d] = v;
        }
    }
}

// ---------------------------------------------------------------------------
// Kernel 2: FeaExt (grouped 3x3) + ReLU + CapsAct (grouped 1x1) -> out
// Tile: 8 rows x 32 cols. 256 threads: (pc = tid&31, n = tid>>5).
// Each thread owns a full column (8 output rows) -> weight loads amortize 8x.
// s_v padded to 66 floats/pixel (stride 66 mod 32 banks = 2 -> 2-way max).
// ---------------------------------------------------------------------------
#define SVP 66
#define K2_SMEM_FLOATS (340 * SVP + 4608 + 512 + 64 + 64)
#define K2_SMEM_BYTES  (K2_SMEM_FLOATS * 4)

__global__ __launch_bounds__(256, 2)
void convcaps_k2(const float* __restrict__ FW,  // [9][8 d][64] 64 = n*8+e
                 const float* __restrict__ FB,  // [64]
                 const float* __restrict__ CW,  // [8 e][64]    64 = n*8+f
                 const float* __restrict__ CB,  // [64]
                 float* __restrict__ out)       // [B,H,W,64] ch = f*8+n
{
    extern __shared__ float sm2[];
    float* s_v  = sm2;                    // 340*66
    float* s_fw = s_v + 340 * SVP;        // 4608
    float* s_cw = s_fw + 4608;            // 512
    float* s_fb = s_cw + 512;             // 64
    float* s_cb = s_fb + 64;              // 64

    const int tid = threadIdx.x;          // 0..255
    const int pc  = tid & 31;
    const int n   = tid >> 5;

    const int b  = blockIdx.z;
    const int h0 = blockIdx.y * 8;
    const int w0 = blockIdx.x * 32;

    // ---- copy v tile with halo (10 rows x 34 cols), float2 granularity ----
    for (int i = tid; i < 340 * 32; i += 256) {
        int hp = i >> 5;
        int q  = i & 31;
        int row  = hp / 34;
        int colh = hp % 34;
        int gh = h0 + row - 1;
        int gw = w0 + colh - 1;
        float2 val = make_float2(0.f, 0.f);
        if ((unsigned)gh < (unsigned)HH && (unsigned)gw < (unsigned)WW)
            val = *(const float2*)(g_v + (((size_t)(b * HH + gh) * WW + gw) * 64) + q * 2);
        *(float2*)(s_v + hp * SVP + q * 2) = val;
    }
    // weights
    for (int i = tid; i < 1152; i += 256) ((float4*)s_fw)[i] = __ldg((const float4*)FW + i);
    if (tid < 128) ((float4*)s_cw)[tid] = __ldg((const float4*)CW + tid);
    if (tid < 64) { s_fb[tid] = __ldg(FB + tid); s_cb[tid] = __ldg(CB + tid); }
    __syncthreads();

    // FeaExt accumulators: 8 rows (pr) x 8 e packed
    ull h1[8][4];
    {
        const ulonglong2* fb = (const ulonglong2*)(s_fb + n * 8);
        ulonglong2 f0 = fb[0], f1 = fb[1];
        #pragma unroll
        for (int pr = 0; pr < 8; pr++) {
            h1[pr][0] = f0.x; h1[pr][1] = f0.y;
            h1[pr][2] = f1.x; h1[pr][3] = f1.y;
        }
    }

    #pragma unroll
    for (int tap = 0; tap < 9; tap++) {
        const int ky = tap / 3, kx = tap % 3;
        const float* vbase = s_v + (ky * 34 + pc + kx) * SVP + n * 8;
        #pragma unroll
        for (int d = 0; d < 8; d++) {
            const ulonglong2* wp = (const ulonglong2*)(s_fw + (tap * 8 + d) * 64 + n * 8);
            ulonglong2 wA = wp[0], wB = wp[1];   // broadcast across warp
            const float* vp = vbase + d;
            #pragma unroll
            for (int pr = 0; pr < 8; pr++) {
                float iv = vp[pr * (34 * SVP)];
                ull iv2; PACK2(iv2, iv, iv);
                FFMA2(h1[pr][0], iv2, wA.x, h1[pr][0]);
                FFMA2(h1[pr][1], iv2, wA.y, h1[pr][1]);
                FFMA2(h1[pr][2], iv2, wB.x, h1[pr][2]);
                FFMA2(h1[pr][3], iv2, wB.y, h1[pr][3]);
            }
        }
    }

    // ---- per row: ReLU + CapsAct + store ----
    const ulonglong2* cbp = (const ulonglong2*)(s_cb + n * 8);
    ulonglong2 cb0 = cbp[0], cb1 = cbp[1];

    #pragma unroll
    for (int pr = 0; pr < 8; pr++) {
        float e[8];
        #pragma unroll
        for (int j = 0; j < 4; j++)
            UNPACK2(e[2 * j], e[2 * j + 1], h1[pr][j]);
        #pragma unroll
        for (int k = 0; k < 8; k++) e[k] = fmaxf(e[k], 0.f);

        ull h2[4] = {cb0.x, cb0.y, cb1.x, cb1.y};
        #pragma unroll
        for (int k = 0; k < 8; k++) {
            ull he2; PACK2(he2, e[k], e[k]);
            const ulonglong2* cwp = (const ulonglong2*)(s_cw + k * 64 + n * 8);
            ulonglong2 cA = cwp[0], cB = cwp[1];
            FFMA2(h2[0], he2, cA.x, h2[0]);
            FFMA2(h2[1], he2, cA.y, h2[1]);
            FFMA2(h2[2], he2, cB.x, h2[2]);
            FFMA2(h2[3], he2, cB.y, h2[3]);
        }

        float r[8];
        #pragma unroll
        for (int j = 0; j < 4; j++)
            UNPACK2(r[2 * j], r[2 * j + 1], h2[j]);

        const int gh = h0 + pr, gw = w0 + pc;
        float* ob = out + ((size_t)(b * HH + gh) * WW + gw) * 64;
        #pragma unroll
        for (int f = 0; f < 8; f++)
            ob[f * 8 + n] = r[f];
    }
}

// ---------------------------------------------------------------------------
extern "C" void kernel_launch(void* const* d_in, const int* in_sizes, int n_in,
                              void* d_out, int out_size) {
    (void)in_sizes; (void)n_in; (void)out_size;
    const float* x   = (const float*)d_in[0];
    const float* AW  = (const float*)d_in[1];
    const float* CTW = (const float*)d_in[2];
    const float* CTB = (const float*)d_in[3];
    const float* FW  = (const float*)d_in[4];
    const float* FB  = (const float*)d_in[5];
    const float* CW  = (const float*)d_in[6];
    const float* CB  = (const float*)d_in[7];

    cudaFuncSetAttribute(convcaps_k1,
                         cudaFuncAttributeMaxDynamicSharedMemorySize, K1_SMEM_BYTES);
    cudaFuncSetAttribute(convcaps_k2,
                         cudaFuncAttributeMaxDynamicSharedMemorySize, K2_SMEM_BYTES);

    dim3 grid1(WW / 8, HH / 8, BB);
    convcaps_k1<<<grid1, dim3(64, 16), K1_SMEM_BYTES>>>(x, AW, CTW, CTB);

    dim3 grid2(WW / 32, HH / 8, BB);
    convcaps_k2<<<grid2, 256, K2_SMEM_BYTES>>>(FW, FB, CW, CB, (float*)d_out);
}